// round 15
// baseline (speedup 1.0000x reference)
#include <cuda_runtime.h>
#include <cstdint>

// Problem constants (fixed shapes from setup_inputs)
#define BB 64
#define CC 3
#define HH 224
#define WW 224
#define CW (CC * WW)          // 672
#define NN 224                // Gram size
#define TAIL 45               // 224 - int(0.8*224)
#define NSWEEP 8              // cap; early-exit may trigger sooner
#define THR 1e-9f             // relative skip threshold (cos^2)

// Scratch (device globals: allocation-free per harness rules)
__device__ float g_A[BB * HH * CW];     // masked, scaled input  [b][h][cw]
__device__ float g_G[BB * NN * NN];     // Gram A A^T per image
__device__ float g_Ut[BB * TAIL * NN];  // tail eigenvectors, row t = u_t^T
__device__ int   g_cnt[BB];             // observed-entry counts

// ---- packed f32x2 helpers (ptxas never emits FFMA2 from plain C++) --------
__device__ __forceinline__ unsigned long long pk2(float lo, float hi) {
    unsigned long long r;
    asm("mov.b64 %0, {%1, %2};" : "=l"(r) : "f"(lo), "f"(hi));
    return r;
}
__device__ __forceinline__ void upk2(unsigned long long v, float& lo, float& hi) {
    asm("mov.b64 {%0, %1}, %2;" : "=f"(lo), "=f"(hi) : "l"(v));
}
__device__ __forceinline__ unsigned long long fma2_(unsigned long long a,
                                                    unsigned long long b,
                                                    unsigned long long c) {
    unsigned long long r;
    asm("fma.rn.f32x2 %0, %1, %2, %3;" : "=l"(r) : "l"(a), "l"(b), "l"(c));
    return r;
}
__device__ __forceinline__ unsigned long long mul2_(unsigned long long a,
                                                    unsigned long long b) {
    unsigned long long r;
    asm("mul.rn.f32x2 %0, %1, %2;" : "=l"(r) : "l"(a), "l"(b));
    return r;
}
__device__ __forceinline__ unsigned long long add2_(unsigned long long a,
                                                    unsigned long long b) {
    unsigned long long r;
    asm("add.rn.f32x2 %0, %1, %2;" : "=l"(r) : "l"(a), "l"(b));
    return r;
}

// ---------------------------------------------------------------------------
// K1: A = (2x-1)*mask in [B,H,CW] layout; per-image mask count via atomics.
// ---------------------------------------------------------------------------
__global__ void build_kernel(const float* __restrict__ x,
                             const int* __restrict__ mask) {
    int idx = blockIdx.x * 256 + threadIdx.x;
    int b   = idx / (HH * CW);
    int rem = idx - b * (HH * CW);
    int h   = rem / CW;
    int cw  = rem - h * CW;
    int c   = cw / WW;
    int w   = cw - c * WW;

    int m = mask[idx];
    float xv = x[((b * CC + c) * HH + h) * WW + w];
    g_A[idx] = m ? (2.0f * xv - 1.0f) : 0.0f;

    int s = m;
    #pragma unroll
    for (int o = 16; o; o >>= 1) s += __shfl_xor_sync(0xffffffffu, s, o);
    __shared__ int ss[8];
    int warp = threadIdx.x >> 5, lane = threadIdx.x & 31;
    if (lane == 0) ss[warp] = s;
    __syncthreads();
    if (threadIdx.x == 0) {
        int t = 0;
        #pragma unroll
        for (int i = 0; i < 8; i++) t += ss[i];
        atomicAdd(&g_cnt[b], t);
    }
}

// ---------------------------------------------------------------------------
// K2: G = A A^T per image. grid (7,7,BB), block (16,16), 2x2 micro-tile.
// ---------------------------------------------------------------------------
__global__ void gram_kernel() {
    __shared__ float As[32][33];
    __shared__ float Bs[32][33];
    int b  = blockIdx.z;
    int i0 = blockIdx.y * 32, j0 = blockIdx.x * 32;
    const float* Ab = g_A + (size_t)b * HH * CW;
    int tx = threadIdx.x, ty = threadIdx.y;
    int t = ty * 16 + tx;

    float a00 = 0.f, a01 = 0.f, a10 = 0.f, a11 = 0.f;
    for (int k0 = 0; k0 < CW; k0 += 32) {
        #pragma unroll
        for (int q = 0; q < 4; q++) {
            int e = t + q * 256;
            int rr = e >> 5, kk = e & 31;
            As[rr][kk] = Ab[(i0 + rr) * CW + k0 + kk];
            Bs[rr][kk] = Ab[(j0 + rr) * CW + k0 + kk];
        }
        __syncthreads();
        #pragma unroll
        for (int kk = 0; kk < 32; kk++) {
            float x0 = As[2 * ty][kk], x1 = As[2 * ty + 1][kk];
            float y0 = Bs[2 * tx][kk], y1 = Bs[2 * tx + 1][kk];
            a00 += x0 * y0; a01 += x0 * y1;
            a10 += x1 * y0; a11 += x1 * y1;
        }
        __syncthreads();
    }
    float* Gb = g_G + (size_t)b * NN * NN;
    Gb[(i0 + 2 * ty    ) * NN + j0 + 2 * tx    ] = a00;
    Gb[(i0 + 2 * ty    ) * NN + j0 + 2 * tx + 1] = a01;
    Gb[(i0 + 2 * ty + 1) * NN + j0 + 2 * tx    ] = a10;
    Gb[(i0 + 2 * ty + 1) * NN + j0 + 2 * tx + 1] = a11;
}

// ---------------------------------------------------------------------------
// K3: one-sided Jacobi, 8-lane-group SIMD + packed f32x2 math.
// 896 threads = 112 groups of 8 lanes; group g handles pair g of the round.
// Columns as ulonglong2 (128-bit LDS/STS); dot + rotate in fma.rn.f32x2.
// Tournament: round r pairs (223, r) and ((r+p)%223, (r-p)%223).
// ---------------------------------------------------------------------------
__device__ __forceinline__ void pair_ij(int r, int p, int& i, int& j) {
    if (p == 0) { i = NN - 1; j = r; }
    else {
        i = r + p; if (i >= NN - 1) i -= (NN - 1);
        j = r - p; if (j < 0)       j += (NN - 1);
    }
}

__global__ void __launch_bounds__(896, 1) jacobi_kernel() {
    extern __shared__ float sm[];
    float* W   = sm;                    // NN*NN, column-major
    float* nrm = sm + NN * NN;          // NN squared norms (maintained)
    int*   rnk = (int*)(nrm + NN);      // NN ranks
    __shared__ int rot_flag;

    int b = blockIdx.x;
    int tid = threadIdx.x, warp = tid >> 5, lane = tid & 31;
    int gl = lane & 7;                  // lane within 8-lane group
    int p  = (warp << 2) | (lane >> 3); // pair id 0..111
    const float* Gb = g_G + (size_t)b * NN * NN;

    for (int i = tid; i < NN * NN; i += 896) W[i] = Gb[i];
    __syncthreads();

    // initial column squared norms: 8 cols per warp, full-warp reduce
    #pragma unroll
    for (int k = 0; k < 8; k++) {
        int col = warp * 8 + k;
        const float* cc = W + col * NN;
        float s = 0.f;
        #pragma unroll
        for (int m = 0; m < 7; m++) { float v = cc[lane + 32 * m]; s += v * v; }
        #pragma unroll
        for (int o = 16; o; o >>= 1) s += __shfl_xor_sync(0xffffffffu, s, o);
        if (lane == 0) nrm[col] = s;
    }
    __syncthreads();

    for (int sw = 0; sw < NSWEEP; ++sw) {
        if (tid == 0) rot_flag = 0;
        __syncthreads();
        for (int r = 0; r < NN - 1; ++r) {
            int i, j; pair_ij(r, p, i, j);
            ulonglong2* ci = (ulonglong2*)(W + i * NN);
            ulonglong2* cj = (ulonglong2*)(W + j * NN);

            // dot over the group's 28-element slices; hold BOTH columns
            ulonglong2 wi[7], wj[7];
            unsigned long long acc0 = 0ull, acc1 = 0ull;  // packed (0,0)
            #pragma unroll
            for (int m = 0; m < 7; m++) {
                ulonglong2 a = ci[gl + 8 * m];
                ulonglong2 u = cj[gl + 8 * m];
                wi[m] = a; wj[m] = u;
                acc0 = fma2_(a.x, u.x, acc0);
                acc1 = fma2_(a.y, u.y, acc1);
            }
            acc0 = add2_(acc0, acc1);
            float plo, phi; upk2(acc0, plo, phi);
            float pp = plo + phi;
            pp += __shfl_xor_sync(0xffffffffu, pp, 4);
            pp += __shfl_xor_sync(0xffffffffu, pp, 2);
            pp += __shfl_xor_sync(0xffffffffu, pp, 1);

            float qi = nrm[i], qj = nrm[j];
            if (pp * pp > THR * qi * qj) {     // uniform within group
                float tau = (qj - qi) / (2.0f * pp);
                float tt = 1.0f / (fabsf(tau) + sqrtf(1.0f + tau * tau));
                if (tau < 0.f) tt = -tt;
                float c = rsqrtf(1.0f + tt * tt);
                float s = c * tt;
                unsigned long long c2  = pk2(c, c);
                unsigned long long s2  = pk2(s, s);
                unsigned long long ns2 = pk2(-s, -s);
                #pragma unroll
                for (int m = 0; m < 7; m++) {
                    ulonglong2 a = wi[m], u = wj[m];
                    ulonglong2 ni, nj;
                    ni.x = fma2_(c2, a.x, mul2_(ns2, u.x));
                    ni.y = fma2_(c2, a.y, mul2_(ns2, u.y));
                    nj.x = fma2_(c2, u.x, mul2_(s2, a.x));
                    nj.y = fma2_(c2, u.y, mul2_(s2, a.y));
                    ci[gl + 8 * m] = ni;
                    cj[gl + 8 * m] = nj;
                }
                if (gl == 0) {
                    float c2s = c * c, s2s = s * s, cs2 = 2.f * c * s;
                    nrm[i] = c2s * qi - cs2 * pp + s2s * qj;
                    nrm[j] = s2s * qi + cs2 * pp + c2s * qj;
                    rot_flag = 1;
                }
            }
            __syncthreads();
        }
        int done = (rot_flag == 0);
        __syncthreads();        // all reads of flag precede next reset
        if (done) break;
    }

    // rank of each column (0 = smallest norm), deterministic tie-break
    if (tid < NN) {
        float mine = nrm[tid];
        int rk = 0;
        for (int j = 0; j < NN; j++) {
            float o = nrm[j];
            rk += (o < mine) || (o == mine && j < tid);
        }
        rnk[tid] = rk;
    }
    __syncthreads();

    // write normalized tail-45 eigenvectors (rows of Ut^T), coalesced
    for (int t = 0; t < NN; t++) {
        int rk = rnk[t];
        if (rk < TAIL) {
            float inv = rsqrtf(nrm[t]);   // 1/lambda
            for (int rr = tid; rr < NN; rr += 896)
                g_Ut[((size_t)b * TAIL + rk) * NN + rr] = W[t * NN + rr] * inv;
        }
    }
}

// ---------------------------------------------------------------------------
// K4: R = A - Ut (Ut^T A); epilogue: /p_obs, clip, (r+1)/2, scatter to NCHW.
// Two CTAs per image (336 columns each), T in 45 registers/thread.
// ---------------------------------------------------------------------------
__global__ void __launch_bounds__(336, 2) recon_kernel(float* __restrict__ out) {
    __shared__ __align__(16) float sU[TAIL * NN];
    int b = blockIdx.x >> 1, half = blockIdx.x & 1;
    int tid = threadIdx.x;
    int cw  = half * 336 + tid;
    const float* Ub = g_Ut + (size_t)b * TAIL * NN;
    for (int i = tid; i < TAIL * NN; i += 336) sU[i] = Ub[i];
    __syncthreads();

    const float* Ab = g_A + (size_t)b * HH * CW;
    float inv_p = (float)(HH * CW) / (float)g_cnt[b];

    float acc[TAIL];
    #pragma unroll
    for (int t = 0; t < TAIL; t++) acc[t] = 0.f;

    for (int h = 0; h < HH; h += 4) {
        float a0 = Ab[(h + 0) * CW + cw];
        float a1 = Ab[(h + 1) * CW + cw];
        float a2 = Ab[(h + 2) * CW + cw];
        float a3 = Ab[(h + 3) * CW + cw];
        #pragma unroll
        for (int t = 0; t < TAIL; t++) {
            float4 u = *(const float4*)&sU[t * NN + h];
            acc[t] += u.x * a0 + u.y * a1 + u.z * a2 + u.w * a3;
        }
    }

    int c = cw / WW, w = cw - c * WW;
    float* ob = out + (((size_t)b * CC + c) * HH) * WW + w;

    for (int h = 0; h < HH; h += 4) {
        float a0 = Ab[(h + 0) * CW + cw];
        float a1 = Ab[(h + 1) * CW + cw];
        float a2 = Ab[(h + 2) * CW + cw];
        float a3 = Ab[(h + 3) * CW + cw];
        float s0 = 0.f, s1 = 0.f, s2 = 0.f, s3 = 0.f;
        #pragma unroll
        for (int t = 0; t < TAIL; t++) {
            float4 u = *(const float4*)&sU[t * NN + h];
            float tv = acc[t];
            s0 += u.x * tv; s1 += u.y * tv; s2 += u.z * tv; s3 += u.w * tv;
        }
        float r0 = (a0 - s0) * inv_p;
        float r1 = (a1 - s1) * inv_p;
        float r2 = (a2 - s2) * inv_p;
        float r3 = (a3 - s3) * inv_p;
        r0 = fminf(1.f, fmaxf(-1.f, r0));
        r1 = fminf(1.f, fmaxf(-1.f, r1));
        r2 = fminf(1.f, fmaxf(-1.f, r2));
        r3 = fminf(1.f, fmaxf(-1.f, r3));
        ob[(h + 0) * WW] = 0.5f * r0 + 0.5f;
        ob[(h + 1) * WW] = 0.5f * r1 + 0.5f;
        ob[(h + 2) * WW] = 0.5f * r2 + 0.5f;
        ob[(h + 3) * WW] = 0.5f * r3 + 0.5f;
    }
}

// ---------------------------------------------------------------------------
extern "C" void kernel_launch(void* const* d_in, const int* in_sizes, int n_in,
                              void* d_out, int out_size) {
    const float* x    = (const float*)d_in[0];
    const int*   mask = (const int*)d_in[1];
    float*       out  = (float*)d_out;

    const int JAC_SMEM = (NN * NN + NN) * (int)sizeof(float) + NN * (int)sizeof(int);

    void* cntp = nullptr;
    cudaGetSymbolAddress(&cntp, g_cnt);
    cudaMemsetAsync(cntp, 0, BB * sizeof(int));

    cudaFuncSetAttribute(jacobi_kernel,
                         cudaFuncAttributeMaxDynamicSharedMemorySize, JAC_SMEM);

    build_kernel<<<BB * HH * CW / 256, 256>>>(x, mask);
    gram_kernel<<<dim3(7, 7, BB), dim3(16, 16)>>>();
    jacobi_kernel<<<BB, 896, JAC_SMEM>>>();
    recon_kernel<<<2 * BB, 336>>>(out);
}

// round 16
// speedup vs baseline: 1.0781x; 1.0781x over previous
#include <cuda_runtime.h>
#include <cstdint>

// Problem constants (fixed shapes from setup_inputs)
#define BB 64
#define CC 3
#define HH 224
#define WW 224
#define CW (CC * WW)          // 672
#define NN 224                // Gram size
#define TAIL 45               // 224 - int(0.8*224)
#define NSWEEP 8              // cap; early-exit may trigger sooner
#define THR 1e-9f             // relative skip threshold (cos^2)

// Scratch (device globals: allocation-free per harness rules)
__device__ float g_A[BB * HH * CW];     // masked, scaled input  [b][h][cw]
__device__ float g_G[BB * NN * NN];     // Gram A A^T per image
__device__ float g_Ut[BB * TAIL * NN];  // tail eigenvectors, row t = u_t^T
__device__ int   g_cnt[BB];             // observed-entry counts

// ---------------------------------------------------------------------------
// K1: A = (2x-1)*mask in [B,H,CW] layout; per-image mask count via atomics.
// ---------------------------------------------------------------------------
__global__ void build_kernel(const float* __restrict__ x,
                             const int* __restrict__ mask) {
    int idx = blockIdx.x * 256 + threadIdx.x;
    int b   = idx / (HH * CW);
    int rem = idx - b * (HH * CW);
    int h   = rem / CW;
    int cw  = rem - h * CW;
    int c   = cw / WW;
    int w   = cw - c * WW;

    int m = mask[idx];
    float xv = x[((b * CC + c) * HH + h) * WW + w];
    g_A[idx] = m ? (2.0f * xv - 1.0f) : 0.0f;

    int s = m;
    #pragma unroll
    for (int o = 16; o; o >>= 1) s += __shfl_xor_sync(0xffffffffu, s, o);
    __shared__ int ss[8];
    int warp = threadIdx.x >> 5, lane = threadIdx.x & 31;
    if (lane == 0) ss[warp] = s;
    __syncthreads();
    if (threadIdx.x == 0) {
        int t = 0;
        #pragma unroll
        for (int i = 0; i < 8; i++) t += ss[i];
        atomicAdd(&g_cnt[b], t);
    }
}

// ---------------------------------------------------------------------------
// K2: G = A A^T per image. grid (7,7,BB), block (16,16), 2x2 micro-tile.
// ---------------------------------------------------------------------------
__global__ void gram_kernel() {
    __shared__ float As[32][33];
    __shared__ float Bs[32][33];
    int b  = blockIdx.z;
    int i0 = blockIdx.y * 32, j0 = blockIdx.x * 32;
    const float* Ab = g_A + (size_t)b * HH * CW;
    int tx = threadIdx.x, ty = threadIdx.y;
    int t = ty * 16 + tx;

    float a00 = 0.f, a01 = 0.f, a10 = 0.f, a11 = 0.f;
    for (int k0 = 0; k0 < CW; k0 += 32) {
        #pragma unroll
        for (int q = 0; q < 4; q++) {
            int e = t + q * 256;
            int rr = e >> 5, kk = e & 31;
            As[rr][kk] = Ab[(i0 + rr) * CW + k0 + kk];
            Bs[rr][kk] = Ab[(j0 + rr) * CW + k0 + kk];
        }
        __syncthreads();
        #pragma unroll
        for (int kk = 0; kk < 32; kk++) {
            float x0 = As[2 * ty][kk], x1 = As[2 * ty + 1][kk];
            float y0 = Bs[2 * tx][kk], y1 = Bs[2 * tx + 1][kk];
            a00 += x0 * y0; a01 += x0 * y1;
            a10 += x1 * y0; a11 += x1 * y1;
        }
        __syncthreads();
    }
    float* Gb = g_G + (size_t)b * NN * NN;
    Gb[(i0 + 2 * ty    ) * NN + j0 + 2 * tx    ] = a00;
    Gb[(i0 + 2 * ty    ) * NN + j0 + 2 * tx + 1] = a01;
    Gb[(i0 + 2 * ty + 1) * NN + j0 + 2 * tx    ] = a10;
    Gb[(i0 + 2 * ty + 1) * NN + j0 + 2 * tx + 1] = a11;
}

// ---------------------------------------------------------------------------
// K3: one-sided Jacobi, 8-lane-group SIMD, sorted pairing (de Rijk-style).
// 896 threads = 112 groups of 8 lanes; group g handles pair g of the round.
// Tournament runs over POSITIONS; prm[pos] maps to the actual column,
// ordered by descending initial norm (classical pivot heuristic — faster
// convergence, zero data movement). Columns as 7 float4 per lane.
// Incremental norms; relative skip threshold; early exit on clean sweep.
// ---------------------------------------------------------------------------
__device__ __forceinline__ void pair_ij(int r, int p, int& i, int& j) {
    if (p == 0) { i = NN - 1; j = r; }
    else {
        i = r + p; if (i >= NN - 1) i -= (NN - 1);
        j = r - p; if (j < 0)       j += (NN - 1);
    }
}

__global__ void __launch_bounds__(896, 1) jacobi_kernel() {
    extern __shared__ float sm[];
    float* W   = sm;                    // NN*NN, column-major
    float* nrm = sm + NN * NN;          // NN squared norms (maintained)
    int*   prm = (int*)(nrm + NN);      // NN position->column (desc norm)
    int*   rnk = prm + NN;              // NN ranks (final tail select)
    __shared__ int rot_flag;

    int b = blockIdx.x;
    int tid = threadIdx.x, warp = tid >> 5, lane = tid & 31;
    int gl = lane & 7;                  // lane within 8-lane group
    int p  = (warp << 2) | (lane >> 3); // pair id 0..111
    const float* Gb = g_G + (size_t)b * NN * NN;

    for (int i = tid; i < NN * NN; i += 896) W[i] = Gb[i];
    __syncthreads();

    // initial column squared norms: 8 cols per warp, full-warp reduce
    #pragma unroll
    for (int k = 0; k < 8; k++) {
        int col = warp * 8 + k;
        const float* cc = W + col * NN;
        float s = 0.f;
        #pragma unroll
        for (int m = 0; m < 7; m++) { float v = cc[lane + 32 * m]; s += v * v; }
        #pragma unroll
        for (int o = 16; o; o >>= 1) s += __shfl_xor_sync(0xffffffffu, s, o);
        if (lane == 0) nrm[col] = s;
    }
    __syncthreads();

    // descending-norm permutation: prm[rank] = column (deterministic ties)
    if (tid < NN) {
        float mine = nrm[tid];
        int rk = 0;
        for (int j = 0; j < NN; j++) {
            float o = nrm[j];
            rk += (o > mine) || (o == mine && j < tid);
        }
        prm[rk] = tid;
    }
    __syncthreads();

    for (int sw = 0; sw < NSWEEP; ++sw) {
        if (tid == 0) rot_flag = 0;
        __syncthreads();
        for (int r = 0; r < NN - 1; ++r) {
            int ip, jp; pair_ij(r, p, ip, jp);
            int i = prm[ip], j = prm[jp];
            float4* ci = (float4*)(W + i * NN);
            float4* cj = (float4*)(W + j * NN);

            // dot over the group's 28-element slices; hold BOTH columns
            float4 wi[7], wj[7];
            float pp = 0.f;
            #pragma unroll
            for (int m = 0; m < 7; m++) {
                float4 a = ci[gl + 8 * m];
                float4 u = cj[gl + 8 * m];
                wi[m] = a; wj[m] = u;
                pp += a.x * u.x + a.y * u.y + a.z * u.z + a.w * u.w;
            }
            pp += __shfl_xor_sync(0xffffffffu, pp, 4);
            pp += __shfl_xor_sync(0xffffffffu, pp, 2);
            pp += __shfl_xor_sync(0xffffffffu, pp, 1);

            float qi = nrm[i], qj = nrm[j];
            if (pp * pp > THR * qi * qj) {     // uniform within group
                float tau = (qj - qi) / (2.0f * pp);
                float tt = 1.0f / (fabsf(tau) + sqrtf(1.0f + tau * tau));
                if (tau < 0.f) tt = -tt;
                float c = rsqrtf(1.0f + tt * tt);
                float s = c * tt;
                #pragma unroll
                for (int m = 0; m < 7; m++) {
                    float4 a = wi[m], u = wj[m];
                    float4 ni, nj;
                    ni.x = c * a.x - s * u.x;  nj.x = s * a.x + c * u.x;
                    ni.y = c * a.y - s * u.y;  nj.y = s * a.y + c * u.y;
                    ni.z = c * a.z - s * u.z;  nj.z = s * a.z + c * u.z;
                    ni.w = c * a.w - s * u.w;  nj.w = s * a.w + c * u.w;
                    ci[gl + 8 * m] = ni;
                    cj[gl + 8 * m] = nj;
                }
                if (gl == 0) {
                    float c2 = c * c, s2 = s * s, cs2 = 2.f * c * s;
                    nrm[i] = c2 * qi - cs2 * pp + s2 * qj;
                    nrm[j] = s2 * qi + cs2 * pp + c2 * qj;
                    rot_flag = 1;
                }
            }
            __syncthreads();
        }
        int done = (rot_flag == 0);
        __syncthreads();        // all reads of flag precede next reset
        if (done) break;
    }

    // rank of each column (0 = smallest norm), deterministic tie-break
    if (tid < NN) {
        float mine = nrm[tid];
        int rk = 0;
        for (int j = 0; j < NN; j++) {
            float o = nrm[j];
            rk += (o < mine) || (o == mine && j < tid);
        }
        rnk[tid] = rk;
    }
    __syncthreads();

    // write normalized tail-45 eigenvectors (rows of Ut^T), coalesced
    for (int t = 0; t < NN; t++) {
        int rk = rnk[t];
        if (rk < TAIL) {
            float inv = rsqrtf(nrm[t]);   // 1/lambda
            for (int rr = tid; rr < NN; rr += 896)
                g_Ut[((size_t)b * TAIL + rk) * NN + rr] = W[t * NN + rr] * inv;
        }
    }
}

// ---------------------------------------------------------------------------
// K4: R = A - Ut (Ut^T A); epilogue: /p_obs, clip, (r+1)/2, scatter to NCHW.
// Two CTAs per image (336 columns each), T in 45 registers/thread.
// ---------------------------------------------------------------------------
__global__ void __launch_bounds__(336, 2) recon_kernel(float* __restrict__ out) {
    __shared__ __align__(16) float sU[TAIL * NN];
    int b = blockIdx.x >> 1, half = blockIdx.x & 1;
    int tid = threadIdx.x;
    int cw  = half * 336 + tid;
    const float* Ub = g_Ut + (size_t)b * TAIL * NN;
    for (int i = tid; i < TAIL * NN; i += 336) sU[i] = Ub[i];
    __syncthreads();

    const float* Ab = g_A + (size_t)b * HH * CW;
    float inv_p = (float)(HH * CW) / (float)g_cnt[b];

    float acc[TAIL];
    #pragma unroll
    for (int t = 0; t < TAIL; t++) acc[t] = 0.f;

    for (int h = 0; h < HH; h += 4) {
        float a0 = Ab[(h + 0) * CW + cw];
        float a1 = Ab[(h + 1) * CW + cw];
        float a2 = Ab[(h + 2) * CW + cw];
        float a3 = Ab[(h + 3) * CW + cw];
        #pragma unroll
        for (int t = 0; t < TAIL; t++) {
            float4 u = *(const float4*)&sU[t * NN + h];
            acc[t] += u.x * a0 + u.y * a1 + u.z * a2 + u.w * a3;
        }
    }

    int c = cw / WW, w = cw - c * WW;
    float* ob = out + (((size_t)b * CC + c) * HH) * WW + w;

    for (int h = 0; h < HH; h += 4) {
        float a0 = Ab[(h + 0) * CW + cw];
        float a1 = Ab[(h + 1) * CW + cw];
        float a2 = Ab[(h + 2) * CW + cw];
        float a3 = Ab[(h + 3) * CW + cw];
        float s0 = 0.f, s1 = 0.f, s2 = 0.f, s3 = 0.f;
        #pragma unroll
        for (int t = 0; t < TAIL; t++) {
            float4 u = *(const float4*)&sU[t * NN + h];
            float tv = acc[t];
            s0 += u.x * tv; s1 += u.y * tv; s2 += u.z * tv; s3 += u.w * tv;
        }
        float r0 = (a0 - s0) * inv_p;
        float r1 = (a1 - s1) * inv_p;
        float r2 = (a2 - s2) * inv_p;
        float r3 = (a3 - s3) * inv_p;
        r0 = fminf(1.f, fmaxf(-1.f, r0));
        r1 = fminf(1.f, fmaxf(-1.f, r1));
        r2 = fminf(1.f, fmaxf(-1.f, r2));
        r3 = fminf(1.f, fmaxf(-1.f, r3));
        ob[(h + 0) * WW] = 0.5f * r0 + 0.5f;
        ob[(h + 1) * WW] = 0.5f * r1 + 0.5f;
        ob[(h + 2) * WW] = 0.5f * r2 + 0.5f;
        ob[(h + 3) * WW] = 0.5f * r3 + 0.5f;
    }
}

// ---------------------------------------------------------------------------
extern "C" void kernel_launch(void* const* d_in, const int* in_sizes, int n_in,
                              void* d_out, int out_size) {
    const float* x    = (const float*)d_in[0];
    const int*   mask = (const int*)d_in[1];
    float*       out  = (float*)d_out;

    // W + nrm + prm + rnk
    const int JAC_SMEM = (NN * NN + NN) * (int)sizeof(float)
                       + 2 * NN * (int)sizeof(int);

    void* cntp = nullptr;
    cudaGetSymbolAddress(&cntp, g_cnt);
    cudaMemsetAsync(cntp, 0, BB * sizeof(int));

    cudaFuncSetAttribute(jacobi_kernel,
                         cudaFuncAttributeMaxDynamicSharedMemorySize, JAC_SMEM);

    build_kernel<<<BB * HH * CW / 256, 256>>>(x, mask);
    gram_kernel<<<dim3(7, 7, BB), dim3(16, 16)>>>();
    jacobi_kernel<<<BB, 896, JAC_SMEM>>>();
    recon_kernel<<<2 * BB, 336>>>(out);
}